// round 6
// baseline (speedup 1.0000x reference)
#include <cuda_runtime.h>

// ---------------------------------------------------------------------------
// DifferentiableRenderer: Gaussian splat weighted-average render.
// out[b,c,y,x] = sum_n w_n*color_n / (sum_n w_n + 1e-8)
// w_n = opacity_n * exp(-0.5*((x-u_n)^2+(y-v_n)^2)/var_n)
//
// R6: compact 32B/gaussian loads (in-loop f32x2 broadcast packs on alu pipe)
//     + SLICES=24 / block=192 / grid=1024 -> 41.5 warps/SM, single wave.
// ---------------------------------------------------------------------------

#define HH 128
#define WW 128
#define HWP (HH * WW)
#define FXC 150.0f
#define FYC 150.0f
#define CXC 64.0f
#define CYC 64.0f
#define EPSC 1e-8f

#define MAXBN 16384   // max B*N entries (B=2, N=4096 -> 8192 used)

typedef unsigned long long ull;

// Compact per-gaussian operands:
__device__ float4 g_ga[MAXBN];  // -u, -v, a, bop
__device__ float4 g_gb[MAXBN];  // cr, cg, cb, 0

__device__ __forceinline__ float ex2f(float x) {
    float y;
    asm("ex2.approx.ftz.f32 %0, %1;" : "=f"(y) : "f"(x));
    return y;
}
__device__ __forceinline__ ull pk(float lo, float hi) {
    ull r; asm("mov.b64 %0, {%1, %2};" : "=l"(r) : "f"(lo), "f"(hi)); return r;
}
__device__ __forceinline__ float2 upk(ull v) {
    float2 r; asm("mov.b64 {%0, %1}, %2;" : "=f"(r.x), "=f"(r.y) : "l"(v)); return r;
}
__device__ __forceinline__ ull addx2(ull a, ull b) {
    ull r; asm("add.rn.f32x2 %0, %1, %2;" : "=l"(r) : "l"(a), "l"(b)); return r;
}
__device__ __forceinline__ ull mulx2(ull a, ull b) {
    ull r; asm("mul.rn.f32x2 %0, %1, %2;" : "=l"(r) : "l"(a), "l"(b)); return r;
}
__device__ __forceinline__ ull fmax2(ull a, ull b, ull c) {
    ull r; asm("fma.rn.f32x2 %0, %1, %2, %3;" : "=l"(r) : "l"(a), "l"(b), "l"(c));
    return r;
}

// ---------------------------------------------------------------------------
// Prep: one thread per (b, n)
// ---------------------------------------------------------------------------
__global__ void prep_kernel(const float* __restrict__ pos,
                            const float* __restrict__ col,
                            const float* __restrict__ opac,
                            const float* __restrict__ scal,
                            const float* __restrict__ qv,
                            const float* __restrict__ tv,
                            int N, int B) {
    int i = blockIdx.x * blockDim.x + threadIdx.x;
    if (i >= N * B) return;
    int b = i / N;
    int n = i - b * N;

    float qw = qv[b * 4 + 0], qx = qv[b * 4 + 1];
    float qy = qv[b * 4 + 2], qz = qv[b * 4 + 3];
    float inv = 1.0f / sqrtf(qw * qw + qx * qx + qy * qy + qz * qz);
    qw *= inv; qx *= inv; qy *= inv; qz *= inv;

    float R00 = 1.0f - 2.0f * (qy * qy + qz * qz);
    float R01 = 2.0f * (qx * qy - qz * qw);
    float R02 = 2.0f * (qx * qz + qy * qw);
    float R10 = 2.0f * (qx * qy + qz * qw);
    float R11 = 1.0f - 2.0f * (qx * qx + qz * qz);
    float R12 = 2.0f * (qy * qz - qx * qw);
    float R20 = 2.0f * (qx * qz - qy * qw);
    float R21 = 2.0f * (qy * qz + qx * qw);
    float R22 = 1.0f - 2.0f * (qx * qx + qy * qy);

    float px = pos[n * 3 + 0], py = pos[n * 3 + 1], pz = pos[n * 3 + 2];
    float cx = R00 * px + R01 * py + R02 * pz + tv[b * 3 + 0];
    float cy = R10 * px + R11 * py + R12 * pz + tv[b * 3 + 1];
    float cz = R20 * px + R21 * py + R22 * pz + tv[b * 3 + 2];

    float invz = 1.0f / cz;
    float u = cx * invz * FXC + CXC;
    float v = cy * invz * FYC + CYC;

    float s = scal[n];
    // a = -0.5 * log2(e) / var   (log2-domain exponent coefficient)
    float a = -0.72134752044448170f / (s * s);
    float bop = log2f(opac[n]);   // fold opacity into the exponent

    g_ga[i] = make_float4(-u, -v, a, bop);
    g_gb[i] = make_float4(col[n * 3 + 0], col[n * 3 + 1], col[n * 3 + 2], 0.0f);
}

// ---------------------------------------------------------------------------
// Render: block = 192 threads = 8 pixel-quads x 24 gaussian slices.
// Each thread handles 4 consecutive pixels (two f32x2 pairs) of one row.
// grid = 1024 blocks -> 6144 warps = 41.5/SM, single wave at 48 regs.
// ---------------------------------------------------------------------------
#define QUADS   8
#define SLICES  24
#define RTHREADS (QUADS * SLICES)

__global__ void __launch_bounds__(RTHREADS, 7)
render_kernel(float* __restrict__ out, int N, int B) {
    __shared__ float4 red[SLICES * QUADS * 4];
    __shared__ float4 red2[QUADS * 4 * 4];

    const int tid   = threadIdx.x;
    const int slice = tid >> 3;       // 0..23 (4 slices per warp -> broadcast loads)
    const int quad  = tid & 7;        // 0..7

    const int gq      = blockIdx.x * QUADS + quad;   // global quad id
    const int pixbase = gq * 4;
    const int b       = pixbase >> 14;               // / 16384
    const int rem     = pixbase & (HWP - 1);         // y*128 + x0
    const float pyf   = (float)(rem >> 7);
    const float px0   = (float)(rem & 127);

    const ull px01 = pk(px0 + 0.0f, px0 + 1.0f);
    const ull px23 = pk(px0 + 2.0f, px0 + 3.0f);

    // Gaussian slice range for this thread
    const int base = b * N;
    const int i0   = (slice * N) / SLICES;
    const int i1   = ((slice + 1) * N) / SLICES;

    ull den01 = 0, den23 = 0;
    ull ar01 = 0, ar23 = 0;
    ull ag01 = 0, ag23 = 0;
    ull ab01 = 0, ab23 = 0;

    #pragma unroll 2
    for (int i = i0; i < i1; i++) {
        const float4 ga = __ldg(&g_ga[base + i]);   // -u, -v, a, bop
        const float4 gb = __ldg(&g_gb[base + i]);   // cr, cg, cb, -

        // scalar column term: c2 = a*dv^2 + log2(op)
        const float dv = pyf + ga.y;
        const float c2 = fmaf(ga.z * dv, dv, ga.w);

        // broadcast packs (alu pipe)
        const ull mu2 = pk(ga.x, ga.x);
        const ull a2  = pk(ga.z, ga.z);
        const ull c22 = pk(c2, c2);

        // packed row terms: e = a*du^2 + c2 for pixel pairs
        const ull du01 = addx2(px01, mu2);
        const ull du23 = addx2(px23, mu2);
        const ull e01  = fmax2(mulx2(a2, du01), du01, c22);
        const ull e23  = fmax2(mulx2(a2, du23), du23, c22);

        const float2 f01 = upk(e01);
        const float2 f23 = upk(e23);
        const float w0 = ex2f(f01.x);
        const float w1 = ex2f(f01.y);
        const float w2 = ex2f(f23.x);
        const float w3 = ex2f(f23.y);

        const ull w01 = pk(w0, w1);
        const ull w23 = pk(w2, w3);

        const ull cr2 = pk(gb.x, gb.x);
        const ull cg2 = pk(gb.y, gb.y);
        const ull cb2 = pk(gb.z, gb.z);

        den01 = addx2(den01, w01);        den23 = addx2(den23, w23);
        ar01  = fmax2(w01, cr2, ar01);    ar23  = fmax2(w23, cr2, ar23);
        ag01  = fmax2(w01, cg2, ag01);    ag23  = fmax2(w23, cg2, ag23);
        ab01  = fmax2(w01, cb2, ab01);    ab23  = fmax2(w23, cb2, ab23);
    }

    // Cross-slice reduction: red[slice][quad][p] = {den,r,g,b}
    {
        const float2 d01 = upk(den01), d23 = upk(den23);
        const float2 r01 = upk(ar01),  r23 = upk(ar23);
        const float2 g01 = upk(ag01),  g23 = upk(ag23);
        const float2 b01 = upk(ab01),  b23 = upk(ab23);
        float4* myred = &red[(slice * QUADS + quad) * 4];
        myred[0] = make_float4(d01.x, r01.x, g01.x, b01.x);
        myred[1] = make_float4(d01.y, r01.y, g01.y, b01.y);
        myred[2] = make_float4(d23.x, r23.x, g23.x, b23.x);
        myred[3] = make_float4(d23.y, r23.y, g23.y, b23.y);
    }
    __syncthreads();

    // Stage 1: 128 threads, each sums 6 slices for one (output, group) pair.
    if (tid < QUADS * 4 * 4) {
        const int o = tid >> 2;          // 0..31  (quad*4 + p)
        const int g = tid & 3;           // 0..3   slice group
        const int q = o >> 2;
        const int p = o & 3;
        float4 acc = make_float4(0.f, 0.f, 0.f, 0.f);
        #pragma unroll
        for (int j = 0; j < SLICES / 4; j++) {
            const int s = g + j * 4;
            const float4 t = red[(s * QUADS + q) * 4 + p];
            acc.x += t.x; acc.y += t.y; acc.z += t.z; acc.w += t.w;
        }
        red2[o * 4 + g] = acc;
    }
    __syncthreads();

    // Stage 2: 32 threads finish, divide, store.
    if (tid < QUADS * 4) {
        const int q = tid >> 2;
        const int p = tid & 3;
        float4 acc = red2[tid * 4 + 0];
        #pragma unroll
        for (int g = 1; g < 4; g++) {
            const float4 t = red2[tid * 4 + g];
            acc.x += t.x; acc.y += t.y; acc.z += t.z; acc.w += t.w;
        }
        const float invd = 1.0f / (acc.x + EPSC);

        const int gq2  = blockIdx.x * QUADS + q;
        const int pb   = gq2 * 4;
        const int bb   = pb >> 14;
        const int pix  = (pb & (HWP - 1)) + p;
        float* ob = out + (size_t)bb * 3 * HWP + pix;
        ob[0]        = acc.y * invd;   // R plane
        ob[HWP]      = acc.z * invd;   // G plane
        ob[2 * HWP]  = acc.w * invd;   // B plane
    }
}

// ---------------------------------------------------------------------------
extern "C" void kernel_launch(void* const* d_in, const int* in_sizes, int n_in,
                              void* d_out, int out_size) {
    const float* positions = (const float*)d_in[0];
    const float* colors    = (const float*)d_in[1];
    const float* opacities = (const float*)d_in[2];
    const float* scales    = (const float*)d_in[3];
    const float* qvec      = (const float*)d_in[4];
    const float* tvec      = (const float*)d_in[5];
    float* out = (float*)d_out;

    const int N = in_sizes[0] / 3;
    const int B = in_sizes[4] / 4;

    const int totalBN = N * B;
    prep_kernel<<<(totalBN + 255) / 256, 256>>>(positions, colors, opacities,
                                                scales, qvec, tvec, N, B);

    const int quads  = B * HWP / 4;          // 4 pixels per quad
    const int blocks = quads / QUADS;        // 8 quads per block -> 1024 blocks
    render_kernel<<<blocks, RTHREADS>>>(out, N, B);
}

// round 7
// speedup vs baseline: 1.1725x; 1.1725x over previous
#include <cuda_runtime.h>

// ---------------------------------------------------------------------------
// DifferentiableRenderer: Gaussian splat weighted-average render.
// out[b,c,y,x] = sum_n w_n*color_n / (sum_n w_n + 1e-8)
// w_n = opacity_n * exp(-0.5*((x-u_n)^2+(y-v_n)^2)/var_n)
//
// R7: 8 pixels/thread (4 f32x2 pairs) -> 2x ILP, loads/interaction halved,
//     interleaved gaussian slicing for L1-friendly warp access.
//     SLICES=32, OCTS=8, block=256, grid=512.
// ---------------------------------------------------------------------------

#define HH 128
#define WW 128
#define HWP (HH * WW)
#define FXC 150.0f
#define FYC 150.0f
#define CXC 64.0f
#define CYC 64.0f
#define EPSC 1e-8f

#define MAXBN 16384   // max B*N entries (B=2, N=4096 -> 8192 used)

typedef unsigned long long ull;

// Compact per-gaussian operands:
__device__ float4 g_ga[MAXBN];  // -u, -v, a, bop
__device__ float4 g_gb[MAXBN];  // cr, cg, cb, 0

__device__ __forceinline__ float ex2f(float x) {
    float y;
    asm("ex2.approx.ftz.f32 %0, %1;" : "=f"(y) : "f"(x));
    return y;
}
__device__ __forceinline__ ull pk(float lo, float hi) {
    ull r; asm("mov.b64 %0, {%1, %2};" : "=l"(r) : "f"(lo), "f"(hi)); return r;
}
__device__ __forceinline__ float2 upk(ull v) {
    float2 r; asm("mov.b64 {%0, %1}, %2;" : "=f"(r.x), "=f"(r.y) : "l"(v)); return r;
}
__device__ __forceinline__ ull addx2(ull a, ull b) {
    ull r; asm("add.rn.f32x2 %0, %1, %2;" : "=l"(r) : "l"(a), "l"(b)); return r;
}
__device__ __forceinline__ ull mulx2(ull a, ull b) {
    ull r; asm("mul.rn.f32x2 %0, %1, %2;" : "=l"(r) : "l"(a), "l"(b)); return r;
}
__device__ __forceinline__ ull fmax2(ull a, ull b, ull c) {
    ull r; asm("fma.rn.f32x2 %0, %1, %2, %3;" : "=l"(r) : "l"(a), "l"(b), "l"(c));
    return r;
}

// ---------------------------------------------------------------------------
// Prep: one thread per (b, n)
// ---------------------------------------------------------------------------
__global__ void prep_kernel(const float* __restrict__ pos,
                            const float* __restrict__ col,
                            const float* __restrict__ opac,
                            const float* __restrict__ scal,
                            const float* __restrict__ qv,
                            const float* __restrict__ tv,
                            int N, int B) {
    int i = blockIdx.x * blockDim.x + threadIdx.x;
    if (i >= N * B) return;
    int b = i / N;
    int n = i - b * N;

    float qw = qv[b * 4 + 0], qx = qv[b * 4 + 1];
    float qy = qv[b * 4 + 2], qz = qv[b * 4 + 3];
    float inv = 1.0f / sqrtf(qw * qw + qx * qx + qy * qy + qz * qz);
    qw *= inv; qx *= inv; qy *= inv; qz *= inv;

    float R00 = 1.0f - 2.0f * (qy * qy + qz * qz);
    float R01 = 2.0f * (qx * qy - qz * qw);
    float R02 = 2.0f * (qx * qz + qy * qw);
    float R10 = 2.0f * (qx * qy + qz * qw);
    float R11 = 1.0f - 2.0f * (qx * qx + qz * qz);
    float R12 = 2.0f * (qy * qz - qx * qw);
    float R20 = 2.0f * (qx * qz - qy * qw);
    float R21 = 2.0f * (qy * qz + qx * qw);
    float R22 = 1.0f - 2.0f * (qx * qx + qy * qy);

    float px = pos[n * 3 + 0], py = pos[n * 3 + 1], pz = pos[n * 3 + 2];
    float cx = R00 * px + R01 * py + R02 * pz + tv[b * 3 + 0];
    float cy = R10 * px + R11 * py + R12 * pz + tv[b * 3 + 1];
    float cz = R20 * px + R21 * py + R22 * pz + tv[b * 3 + 2];

    float invz = 1.0f / cz;
    float u = cx * invz * FXC + CXC;
    float v = cy * invz * FYC + CYC;

    float s = scal[n];
    // a = -0.5 * log2(e) / var   (log2-domain exponent coefficient)
    float a = -0.72134752044448170f / (s * s);
    float bop = log2f(opac[n]);   // fold opacity into the exponent

    g_ga[i] = make_float4(-u, -v, a, bop);
    g_gb[i] = make_float4(col[n * 3 + 0], col[n * 3 + 1], col[n * 3 + 2], 0.0f);
}

// ---------------------------------------------------------------------------
// Render: block = 256 threads = 8 pixel-octs x 32 gaussian slices.
// Each thread handles 8 consecutive pixels (four f32x2 pairs) of one row.
// Slices are interleaved (i += SLICES) so a warp's loads hit adjacent lines.
// ---------------------------------------------------------------------------
#define OCTS    8
#define SLICES  32
#define RTHREADS (OCTS * SLICES)

__global__ void __launch_bounds__(RTHREADS)
render_kernel(float* __restrict__ out, int N, int B) {
    __shared__ float4 red[SLICES * OCTS * 8];    // 32 KB
    __shared__ float4 red2[OCTS * 8 * 4];        // 4 KB

    const int tid   = threadIdx.x;
    const int slice = tid >> 3;       // 0..31
    const int oct   = tid & 7;        // 0..7

    const int goct    = blockIdx.x * OCTS + oct;   // global oct id
    const int pixbase = goct * 8;
    const int b       = pixbase >> 14;             // / 16384
    const int rem     = pixbase & (HWP - 1);       // y*128 + x0
    const float pyf   = (float)(rem >> 7);
    const float px0   = (float)(rem & 127);

    const ull px01 = pk(px0 + 0.0f, px0 + 1.0f);
    const ull px23 = pk(px0 + 2.0f, px0 + 3.0f);
    const ull px45 = pk(px0 + 4.0f, px0 + 5.0f);
    const ull px67 = pk(px0 + 6.0f, px0 + 7.0f);

    const int base = b * N;

    ull den01 = 0, den23 = 0, den45 = 0, den67 = 0;
    ull ar01 = 0, ar23 = 0, ar45 = 0, ar67 = 0;
    ull ag01 = 0, ag23 = 0, ag45 = 0, ag67 = 0;
    ull ab01 = 0, ab23 = 0, ab45 = 0, ab67 = 0;

    #pragma unroll 2
    for (int i = slice; i < N; i += SLICES) {
        const float4 ga = __ldg(&g_ga[base + i]);   // -u, -v, a, bop
        const float4 gb = __ldg(&g_gb[base + i]);   // cr, cg, cb, -

        // scalar column term: c2 = a*dv^2 + log2(op)
        const float dv = pyf + ga.y;
        const float c2 = fmaf(ga.z * dv, dv, ga.w);

        // broadcast packs (alu pipe), amortized over 8 pixels
        const ull mu2 = pk(ga.x, ga.x);
        const ull a2  = pk(ga.z, ga.z);
        const ull c22 = pk(c2, c2);

        // packed row terms: e = a*du^2 + c2 for pixel pairs
        const ull du01 = addx2(px01, mu2);
        const ull du23 = addx2(px23, mu2);
        const ull du45 = addx2(px45, mu2);
        const ull du67 = addx2(px67, mu2);
        const ull e01  = fmax2(mulx2(a2, du01), du01, c22);
        const ull e23  = fmax2(mulx2(a2, du23), du23, c22);
        const ull e45  = fmax2(mulx2(a2, du45), du45, c22);
        const ull e67  = fmax2(mulx2(a2, du67), du67, c22);

        const float2 f01 = upk(e01);
        const float2 f23 = upk(e23);
        const float2 f45 = upk(e45);
        const float2 f67 = upk(e67);
        const ull w01 = pk(ex2f(f01.x), ex2f(f01.y));
        const ull w23 = pk(ex2f(f23.x), ex2f(f23.y));
        const ull w45 = pk(ex2f(f45.x), ex2f(f45.y));
        const ull w67 = pk(ex2f(f67.x), ex2f(f67.y));

        const ull cr2 = pk(gb.x, gb.x);
        const ull cg2 = pk(gb.y, gb.y);
        const ull cb2 = pk(gb.z, gb.z);

        den01 = addx2(den01, w01);        den23 = addx2(den23, w23);
        den45 = addx2(den45, w45);        den67 = addx2(den67, w67);
        ar01  = fmax2(w01, cr2, ar01);    ar23  = fmax2(w23, cr2, ar23);
        ar45  = fmax2(w45, cr2, ar45);    ar67  = fmax2(w67, cr2, ar67);
        ag01  = fmax2(w01, cg2, ag01);    ag23  = fmax2(w23, cg2, ag23);
        ag45  = fmax2(w45, cg2, ag45);    ag67  = fmax2(w67, cg2, ag67);
        ab01  = fmax2(w01, cb2, ab01);    ab23  = fmax2(w23, cb2, ab23);
        ab45  = fmax2(w45, cb2, ab45);    ab67  = fmax2(w67, cb2, ab67);
    }

    // Write per-slice partials: red[slice][oct][p] = {den, r, g, b}
    {
        float4* myred = &red[(slice * OCTS + oct) * 8];
        const float2 d01 = upk(den01), d23 = upk(den23);
        const float2 d45 = upk(den45), d67 = upk(den67);
        const float2 r01 = upk(ar01),  r23 = upk(ar23);
        const float2 r45 = upk(ar45),  r67 = upk(ar67);
        const float2 g01 = upk(ag01),  g23 = upk(ag23);
        const float2 g45 = upk(ag45),  g67 = upk(ag67);
        const float2 b01 = upk(ab01),  b23 = upk(ab23);
        const float2 b45 = upk(ab45),  b67 = upk(ab67);
        myred[0] = make_float4(d01.x, r01.x, g01.x, b01.x);
        myred[1] = make_float4(d01.y, r01.y, g01.y, b01.y);
        myred[2] = make_float4(d23.x, r23.x, g23.x, b23.x);
        myred[3] = make_float4(d23.y, r23.y, g23.y, b23.y);
        myred[4] = make_float4(d45.x, r45.x, g45.x, b45.x);
        myred[5] = make_float4(d45.y, r45.y, g45.y, b45.y);
        myred[6] = make_float4(d67.x, r67.x, g67.x, b67.x);
        myred[7] = make_float4(d67.y, r67.y, g67.y, b67.y);
    }
    __syncthreads();

    // Stage 1: 256 threads; each sums 8 of 32 slices for one (oct,p) output.
    {
        const int o = tid >> 2;          // 0..63  (oct*8 + p)
        const int g = tid & 3;           // slice group
        const int q = o >> 3;            // oct
        const int p = o & 7;             // pixel in oct
        float4 acc = make_float4(0.f, 0.f, 0.f, 0.f);
        #pragma unroll
        for (int j = 0; j < SLICES / 4; j++) {
            const int s = g + j * 4;
            const float4 t = red[(s * OCTS + q) * 8 + p];
            acc.x += t.x; acc.y += t.y; acc.z += t.z; acc.w += t.w;
        }
        red2[o * 4 + g] = acc;
    }
    __syncthreads();

    // Stage 2: 64 threads finish, divide, store (coalesced: o maps to pix).
    if (tid < OCTS * 8) {
        float4 acc = red2[tid * 4 + 0];
        #pragma unroll
        for (int g = 1; g < 4; g++) {
            const float4 t = red2[tid * 4 + g];
            acc.x += t.x; acc.y += t.y; acc.z += t.z; acc.w += t.w;
        }
        const float invd = 1.0f / (acc.x + EPSC);

        const int gpix = blockIdx.x * (OCTS * 8) + tid;  // global b*HWP + pix
        const int bb   = gpix >> 14;
        const int pix  = gpix & (HWP - 1);
        float* ob = out + (size_t)bb * 3 * HWP + pix;
        ob[0]        = acc.y * invd;   // R plane
        ob[HWP]      = acc.z * invd;   // G plane
        ob[2 * HWP]  = acc.w * invd;   // B plane
    }
}

// ---------------------------------------------------------------------------
extern "C" void kernel_launch(void* const* d_in, const int* in_sizes, int n_in,
                              void* d_out, int out_size) {
    const float* positions = (const float*)d_in[0];
    const float* colors    = (const float*)d_in[1];
    const float* opacities = (const float*)d_in[2];
    const float* scales    = (const float*)d_in[3];
    const float* qvec      = (const float*)d_in[4];
    const float* tvec      = (const float*)d_in[5];
    float* out = (float*)d_out;

    const int N = in_sizes[0] / 3;
    const int B = in_sizes[4] / 4;

    const int totalBN = N * B;
    prep_kernel<<<(totalBN + 255) / 256, 256>>>(positions, colors, opacities,
                                                scales, qvec, tvec, N, B);

    const int octs   = B * HWP / 8;          // 8 pixels per oct
    const int blocks = octs / OCTS;          // 8 octs per block -> 512 blocks
    render_kernel<<<blocks, RTHREADS>>>(out, N, B);
}

// round 8
// speedup vs baseline: 6.5284x; 5.5679x over previous
#include <cuda_runtime.h>

// ---------------------------------------------------------------------------
// DifferentiableRenderer: Gaussian splat weighted-average render.
// out[b,c,y,x] = sum_n w_n*color_n / (sum_n w_n + 1e-8)
// w_n = opacity_n * exp(-0.5*((x-u_n)^2+(y-v_n)^2)/var_n)
//
// R8: tile-based culling. Gaussians are narrow (w < 2^-60 beyond ~4-14 px),
//     so per 16x16 tile only ~5-10% of gaussians matter.
//       k1 prep:   per (b,n) u, v, a=-0.5*log2e/var, bop=log2(op)
//       k2 render: block = (batch, tile, gaussian-slice). Chunked scan of the
//                  slice: conservative tile test -> stable ballot/prefix
//                  compaction into smem -> per-pixel eval of survivors.
//                  Partials to __device__ scratch (deterministic order).
//       k3 merge:  sum SPLIT partials per pixel, divide, store planes.
//     Dropped mass <= N*2^-60 per pixel -> abs error <= ~7e-7 << 1e-3.
// ---------------------------------------------------------------------------

#define HH 128
#define WW 128
#define HWP (HH * WW)
#define FXC 150.0f
#define FYC 150.0f
#define CXC 64.0f
#define CYC 64.0f
#define EPSC 1e-8f

#define TILE    16
#define TX_N    (WW / TILE)          // 8
#define TY_N    (HH / TILE)          // 8
#define TILES   (TX_N * TY_N)        // 64
#define SPLIT   4                    // gaussian slices per tile
#define TPB     256                  // threads per render block (1 px each)
#define CHUNK   256                  // gaussians tested per pass
#define EMIN    (-60.0f)             // log2 weight cutoff

#define MAXBN   16384                // max B*N (B=2, N=4096 -> 8192 used)
#define MAXB    4

// per-gaussian prepared params
__device__ float4 g_ga[MAXBN];       // u, v, a, bop
__device__ float4 g_gb[MAXBN];       // cr, cg, cb, 0
// per (b, tile, split, pixel) partial sums {den, r, g, b}
__device__ float4 g_part[MAXB * TILES * SPLIT * TPB];

__device__ __forceinline__ float ex2f(float x) {
    float y;
    asm("ex2.approx.ftz.f32 %0, %1;" : "=f"(y) : "f"(x));
    return y;
}

// ---------------------------------------------------------------------------
// Prep: one thread per (b, n)
// ---------------------------------------------------------------------------
__global__ void prep_kernel(const float* __restrict__ pos,
                            const float* __restrict__ col,
                            const float* __restrict__ opac,
                            const float* __restrict__ scal,
                            const float* __restrict__ qv,
                            const float* __restrict__ tv,
                            int N, int B) {
    int i = blockIdx.x * blockDim.x + threadIdx.x;
    if (i >= N * B) return;
    int b = i / N;
    int n = i - b * N;

    float qw = qv[b * 4 + 0], qx = qv[b * 4 + 1];
    float qy = qv[b * 4 + 2], qz = qv[b * 4 + 3];
    float inv = 1.0f / sqrtf(qw * qw + qx * qx + qy * qy + qz * qz);
    qw *= inv; qx *= inv; qy *= inv; qz *= inv;

    float R00 = 1.0f - 2.0f * (qy * qy + qz * qz);
    float R01 = 2.0f * (qx * qy - qz * qw);
    float R02 = 2.0f * (qx * qz + qy * qw);
    float R10 = 2.0f * (qx * qy + qz * qw);
    float R11 = 1.0f - 2.0f * (qx * qx + qz * qz);
    float R12 = 2.0f * (qy * qz - qx * qw);
    float R20 = 2.0f * (qx * qz - qy * qw);
    float R21 = 2.0f * (qy * qz + qx * qw);
    float R22 = 1.0f - 2.0f * (qx * qx + qy * qy);

    float px = pos[n * 3 + 0], py = pos[n * 3 + 1], pz = pos[n * 3 + 2];
    float cx = R00 * px + R01 * py + R02 * pz + tv[b * 3 + 0];
    float cy = R10 * px + R11 * py + R12 * pz + tv[b * 3 + 1];
    float cz = R20 * px + R21 * py + R22 * pz + tv[b * 3 + 2];

    float invz = 1.0f / cz;
    float u = cx * invz * FXC + CXC;
    float v = cy * invz * FYC + CYC;

    float s = scal[n];
    // a = -0.5 * log2(e) / var   (log2-domain exponent coefficient)
    float a = -0.72134752044448170f / (s * s);
    float bop = log2f(opac[n]);   // fold opacity into the exponent

    g_ga[i] = make_float4(u, v, a, bop);
    g_gb[i] = make_float4(col[n * 3 + 0], col[n * 3 + 1], col[n * 3 + 2], 0.0f);
}

// ---------------------------------------------------------------------------
// Render: blockIdx.x = ((b*TILES + tile)*SPLIT + s). 256 threads = 1 tile
// of 16x16 pixels. Scan this block's gaussian slice in chunks: test against
// tile bound, compact survivors (stable order), evaluate per pixel.
// ---------------------------------------------------------------------------
__global__ void __launch_bounds__(TPB)
render_tiles(int N) {
    __shared__ float4 sga[CHUNK];
    __shared__ float4 sgb[CHUNK];
    __shared__ int s_wbase[TPB / 32];
    __shared__ int s_wcnt[TPB / 32];
    __shared__ int s_total;

    const int tid  = threadIdx.x;
    const int bid  = blockIdx.x;
    const int s    = bid & (SPLIT - 1);
    const int tile = (bid / SPLIT) & (TILES - 1);
    const int b    = bid / (SPLIT * TILES);

    const int tx = tile & (TX_N - 1);
    const int ty = tile / TX_N;
    const float pxf = (float)(tx * TILE + (tid & (TILE - 1)));
    const float pyf = (float)(ty * TILE + (tid / TILE));
    const float tcx = (float)(tx * TILE) + 7.5f;   // tile center
    const float tcy = (float)(ty * TILE) + 7.5f;

    const int base = b * N;
    const int lo   = (s * N) / SPLIT;
    const int hi   = ((s + 1) * N) / SPLIT;

    const int wid  = tid >> 5;
    const int lane = tid & 31;
    const unsigned lanemask_lt = (1u << lane) - 1u;

    float den = 0.f, ar = 0.f, ag = 0.f, ab = 0.f;

    for (int cb = lo; cb < hi; cb += CHUNK) {
        // --- test CHUNK gaussians (one per thread) against the tile ---
        const int j = cb + tid;
        bool keep = false;
        float4 ga;
        if (j < hi) {
            ga = __ldg(&g_ga[base + j]);           // u, v, a, bop
            float dx = fmaxf(fabsf(ga.x - tcx) - 7.5f, 0.0f);
            float dy = fmaxf(fabsf(ga.y - tcy) - 7.5f, 0.0f);
            float mind2 = dx * dx + dy * dy;
            float emax  = fmaf(ga.z, mind2, ga.w); // a*mind2 + bop (a<0)
            keep = (emax >= EMIN);
        }

        // --- stable compaction (gaussian-index order preserved) ---
        const unsigned mask = __ballot_sync(0xffffffffu, keep);
        if (lane == 0) s_wcnt[wid] = __popc(mask);
        __syncthreads();
        if (tid == 0) {
            int acc = 0;
            #pragma unroll
            for (int w = 0; w < TPB / 32; w++) { s_wbase[w] = acc; acc += s_wcnt[w]; }
            s_total = acc;
        }
        __syncthreads();
        if (keep) {
            const int pos = s_wbase[wid] + __popc(mask & lanemask_lt);
            sga[pos] = ga;
            sgb[pos] = __ldg(&g_gb[base + j]);
        }
        __syncthreads();

        // --- evaluate survivors against this thread's pixel ---
        const int cnt = s_total;
        #pragma unroll 2
        for (int t = 0; t < cnt; t++) {
            const float4 A  = sga[t];              // u, v, a, bop (broadcast)
            const float4 Cc = sgb[t];
            const float dv = pyf - A.y;
            const float c2 = fmaf(A.z * dv, dv, A.w);
            const float du = pxf - A.x;
            const float e  = fmaf(A.z * du, du, c2);
            const float w  = ex2f(e);
            den += w;
            ar = fmaf(w, Cc.x, ar);
            ag = fmaf(w, Cc.y, ag);
            ab = fmaf(w, Cc.z, ab);
        }
        __syncthreads();
    }

    g_part[bid * TPB + tid] = make_float4(den, ar, ag, ab);
}

// ---------------------------------------------------------------------------
// Merge: block per (b, tile); sum SPLIT partials, divide, store 3 planes.
// ---------------------------------------------------------------------------
__global__ void __launch_bounds__(TPB)
merge_kernel(float* __restrict__ out) {
    const int tid = threadIdx.x;
    const int m   = blockIdx.x;            // b*TILES + tile
    const int tile = m & (TILES - 1);
    const int b    = m / TILES;

    float4 acc = g_part[(m * SPLIT + 0) * TPB + tid];
    #pragma unroll
    for (int s = 1; s < SPLIT; s++) {
        const float4 t = g_part[(m * SPLIT + s) * TPB + tid];
        acc.x += t.x; acc.y += t.y; acc.z += t.z; acc.w += t.w;
    }
    const float invd = 1.0f / (acc.x + EPSC);

    const int tx = tile & (TX_N - 1);
    const int ty = tile / TX_N;
    const int px = tx * TILE + (tid & (TILE - 1));
    const int py = ty * TILE + (tid / TILE);
    float* ob = out + (size_t)b * 3 * HWP + py * WW + px;
    ob[0]       = acc.y * invd;   // R plane
    ob[HWP]     = acc.z * invd;   // G plane
    ob[2 * HWP] = acc.w * invd;   // B plane
}

// ---------------------------------------------------------------------------
extern "C" void kernel_launch(void* const* d_in, const int* in_sizes, int n_in,
                              void* d_out, int out_size) {
    const float* positions = (const float*)d_in[0];
    const float* colors    = (const float*)d_in[1];
    const float* opacities = (const float*)d_in[2];
    const float* scales    = (const float*)d_in[3];
    const float* qvec      = (const float*)d_in[4];
    const float* tvec      = (const float*)d_in[5];
    float* out = (float*)d_out;

    const int N = in_sizes[0] / 3;
    const int B = in_sizes[4] / 4;

    const int totalBN = N * B;
    prep_kernel<<<(totalBN + 255) / 256, 256>>>(positions, colors, opacities,
                                                scales, qvec, tvec, N, B);

    render_tiles<<<B * TILES * SPLIT, TPB>>>(N);
    merge_kernel<<<B * TILES, TPB>>>(out);
}

// round 9
// speedup vs baseline: 7.8925x; 1.2090x over previous
#include <cuda_runtime.h>

// ---------------------------------------------------------------------------
// DifferentiableRenderer: Gaussian splat weighted-average render.
// out[b,c,y,x] = sum_n w_n*color_n / (sum_n w_n + 1e-8)
// w_n = opacity_n * exp(-0.5*((x-u_n)^2+(y-v_n)^2)/var_n)
//
// R9: prep fused into the render scan (no prep kernel, no param round-trip).
//     Block = (batch, 16x16 tile, gaussian slice of 8). Per chunk pass each
//     thread preps+culls one gaussian from raw inputs; survivors are stably
//     compacted to smem; 256 pixel-threads evaluate them. Partials merged by
//     a second kernel (deterministic order throughout).
//     Cut at w < 2^-60: per-pixel abs error <= ~7e-7 << 1e-3 budget.
// ---------------------------------------------------------------------------

#define HH 128
#define WW 128
#define HWP (HH * WW)
#define FXC 150.0f
#define FYC 150.0f
#define CXC 64.0f
#define CYC 64.0f
#define EPSC 1e-8f

#define TILE    16
#define TX_N    (WW / TILE)          // 8
#define TY_N    (HH / TILE)          // 8
#define TILES   (TX_N * TY_N)        // 64
#define SPLIT   8                    // gaussian slices per tile
#define TPB     256                  // threads per render block (1 px each)
#define CHUNK   256                  // gaussians prepped+tested per pass
#define EMIN    (-60.0f)             // log2 weight cutoff

#define MAXB    4

// per (b, tile, split, pixel) partial sums {den, r, g, b}
__device__ float4 g_part[MAXB * TILES * SPLIT * TPB];

__device__ __forceinline__ float ex2f(float x) {
    float y;
    asm("ex2.approx.ftz.f32 %0, %1;" : "=f"(y) : "f"(x));
    return y;
}
__device__ __forceinline__ float lg2f(float x) {
    float y;
    asm("lg2.approx.ftz.f32 %0, %1;" : "=f"(y) : "f"(x));
    return y;
}

// ---------------------------------------------------------------------------
// Render: blockIdx.x = ((b*TILES + tile)*SPLIT + s). 256 threads = one 16x16
// pixel tile. Scan this block's gaussian slice in chunks:
//   prep (raw inputs -> u,v,a,bop) -> tile cull -> stable compaction -> eval.
// ---------------------------------------------------------------------------
__global__ void __launch_bounds__(TPB)
render_tiles(const float* __restrict__ pos,
             const float* __restrict__ col,
             const float* __restrict__ opac,
             const float* __restrict__ scal,
             const float* __restrict__ qv,
             const float* __restrict__ tv,
             int N) {
    __shared__ float4 sga[CHUNK];      // u, v, a, bop
    __shared__ float4 sgb[CHUNK];      // cr, cg, cb, -
    __shared__ int s_wbase[TPB / 32];
    __shared__ int s_wcnt[TPB / 32];
    __shared__ int s_total;

    const int tid  = threadIdx.x;
    const int bid  = blockIdx.x;
    const int s    = bid & (SPLIT - 1);
    const int tile = (bid / SPLIT) & (TILES - 1);
    const int b    = bid / (SPLIT * TILES);

    const int tx = tile & (TX_N - 1);
    const int ty = tile / TX_N;
    const float pxf = (float)(tx * TILE + (tid & (TILE - 1)));
    const float pyf = (float)(ty * TILE + (tid / TILE));
    const float tcx = (float)(tx * TILE) + 7.5f;   // tile center
    const float tcy = (float)(ty * TILE) + 7.5f;

    // --- per-batch camera, hoisted (broadcast loads, L1 hits) ---
    float qw = qv[b * 4 + 0], qx = qv[b * 4 + 1];
    float qy = qv[b * 4 + 2], qz = qv[b * 4 + 3];
    {
        float inv = rsqrtf(qw * qw + qx * qx + qy * qy + qz * qz);
        qw *= inv; qx *= inv; qy *= inv; qz *= inv;
    }
    const float R00 = 1.0f - 2.0f * (qy * qy + qz * qz);
    const float R01 = 2.0f * (qx * qy - qz * qw);
    const float R02 = 2.0f * (qx * qz + qy * qw);
    const float R10 = 2.0f * (qx * qy + qz * qw);
    const float R11 = 1.0f - 2.0f * (qx * qx + qz * qz);
    const float R12 = 2.0f * (qy * qz - qx * qw);
    const float R20 = 2.0f * (qx * qz - qy * qw);
    const float R21 = 2.0f * (qy * qz + qx * qw);
    const float R22 = 1.0f - 2.0f * (qx * qx + qy * qy);
    const float t0 = tv[b * 3 + 0], t1 = tv[b * 3 + 1], t2 = tv[b * 3 + 2];

    const int lo = (s * N) / SPLIT;
    const int hi = ((s + 1) * N) / SPLIT;

    const int wid  = tid >> 5;
    const int lane = tid & 31;
    const unsigned lanemask_lt = (1u << lane) - 1u;

    float den = 0.f, ar = 0.f, ag = 0.f, ab = 0.f;

    for (int cb = lo; cb < hi; cb += CHUNK) {
        // --- prep + cull one gaussian per thread ---
        const int j = cb + tid;                    // gaussian index
        bool keep = false;
        float4 ga;
        if (j < hi) {
            const float px = pos[j * 3 + 0];
            const float py = pos[j * 3 + 1];
            const float pz = pos[j * 3 + 2];
            const float cxm = R00 * px + R01 * py + R02 * pz + t0;
            const float cym = R10 * px + R11 * py + R12 * pz + t1;
            const float czm = R20 * px + R21 * py + R22 * pz + t2;
            const float invz = __fdividef(1.0f, czm);
            const float u = cxm * invz * FXC + CXC;
            const float v = cym * invz * FYC + CYC;
            const float sc = scal[j];
            // a = -0.5 * log2(e) / var
            const float a = __fdividef(-0.72134752044448170f, sc * sc);
            const float bop = lg2f(opac[j]);       // opac=0 -> -inf -> culled
            ga = make_float4(u, v, a, bop);

            float dx = fmaxf(fabsf(u - tcx) - 7.5f, 0.0f);
            float dy = fmaxf(fabsf(v - tcy) - 7.5f, 0.0f);
            float mind2 = dx * dx + dy * dy;
            float emax  = fmaf(a, mind2, bop);     // a*mind2 + bop (a<0)
            keep = (emax >= EMIN);
        }

        // --- stable compaction (gaussian-index order preserved) ---
        const unsigned mask = __ballot_sync(0xffffffffu, keep);
        if (lane == 0) s_wcnt[wid] = __popc(mask);
        __syncthreads();
        if (tid == 0) {
            int acc = 0;
            #pragma unroll
            for (int w = 0; w < TPB / 32; w++) { s_wbase[w] = acc; acc += s_wcnt[w]; }
            s_total = acc;
        }
        __syncthreads();
        if (keep) {
            const int posn = s_wbase[wid] + __popc(mask & lanemask_lt);
            sga[posn] = ga;
            sgb[posn] = make_float4(col[j * 3 + 0], col[j * 3 + 1],
                                    col[j * 3 + 2], 0.0f);
        }
        __syncthreads();

        // --- evaluate survivors against this thread's pixel ---
        const int cnt = s_total;
        #pragma unroll 2
        for (int t = 0; t < cnt; t++) {
            const float4 A  = sga[t];              // u, v, a, bop (broadcast)
            const float4 Cc = sgb[t];
            const float dv = pyf - A.y;
            const float c2 = fmaf(A.z * dv, dv, A.w);
            const float du = pxf - A.x;
            const float e  = fmaf(A.z * du, du, c2);
            const float w  = ex2f(e);
            den += w;
            ar = fmaf(w, Cc.x, ar);
            ag = fmaf(w, Cc.y, ag);
            ab = fmaf(w, Cc.z, ab);
        }
        __syncthreads();
    }

    g_part[bid * TPB + tid] = make_float4(den, ar, ag, ab);
}

// ---------------------------------------------------------------------------
// Merge: block per (b, tile); sum SPLIT partials, divide, store 3 planes.
// ---------------------------------------------------------------------------
__global__ void __launch_bounds__(TPB)
merge_kernel(float* __restrict__ out) {
    const int tid = threadIdx.x;
    const int m   = blockIdx.x;            // b*TILES + tile
    const int tile = m & (TILES - 1);
    const int b    = m / TILES;

    float4 acc = g_part[(m * SPLIT + 0) * TPB + tid];
    #pragma unroll
    for (int s = 1; s < SPLIT; s++) {
        const float4 t = g_part[(m * SPLIT + s) * TPB + tid];
        acc.x += t.x; acc.y += t.y; acc.z += t.z; acc.w += t.w;
    }
    const float invd = __fdividef(1.0f, acc.x + EPSC);

    const int tx = tile & (TX_N - 1);
    const int ty = tile / TX_N;
    const int px = tx * TILE + (tid & (TILE - 1));
    const int py = ty * TILE + (tid / TILE);
    float* ob = out + (size_t)b * 3 * HWP + py * WW + px;
    ob[0]       = acc.y * invd;   // R plane
    ob[HWP]     = acc.z * invd;   // G plane
    ob[2 * HWP] = acc.w * invd;   // B plane
}

// ---------------------------------------------------------------------------
extern "C" void kernel_launch(void* const* d_in, const int* in_sizes, int n_in,
                              void* d_out, int out_size) {
    const float* positions = (const float*)d_in[0];
    const float* colors    = (const float*)d_in[1];
    const float* opacities = (const float*)d_in[2];
    const float* scales    = (const float*)d_in[3];
    const float* qvec      = (const float*)d_in[4];
    const float* tvec      = (const float*)d_in[5];
    float* out = (float*)d_out;

    const int N = in_sizes[0] / 3;
    const int B = in_sizes[4] / 4;

    render_tiles<<<B * TILES * SPLIT, TPB>>>(positions, colors, opacities,
                                             scales, qvec, tvec, N);
    merge_kernel<<<B * TILES, TPB>>>(out);
}